// round 2
// baseline (speedup 1.0000x reference)
#include <cuda_runtime.h>

// Problem constants
#define BB 2
#define CC 128
#define GG 8
#define CG 16
#define HH 64
#define WW 64

// Attention tile: 4 rows x 32 cols per block, halo 7 each side
#define TH 4
#define TW 32
#define SH 18              // TH + 14
#define SW 46              // TW + 14
#define CHS (SH*SW)        // 828 floats per channel
#define SMEM_FLOATS (32*CHS + 2*448)
#define SMEM_BYTES (SMEM_FLOATS*4)

// Scratch maps (device globals: allocation-free)
__device__ float g_q[BB*CC*HH*WW];
__device__ float g_k[BB*CC*HH*WW];
__device__ float g_v[BB*CC*HH*WW];

// ---------------------------------------------------------------------------
// Kernel 1: Q/K/V 1x1 conv as tiled GEMM. grid.z: 0=Q(from fm[:,128:]),
// 1=K, 2=V (from fm[:,:128]). Block: 256 threads, 64 pixels x 128 oc.
// ---------------------------------------------------------------------------
__global__ __launch_bounds__(256) void qkv_gemm(
    const float* __restrict__ fm,
    const float* __restrict__ wq,
    const float* __restrict__ wk,
    const float* __restrict__ wv)
{
    __shared__ float wS[128][33];   // [oc][kk], padded
    __shared__ float xS[32][64];    // [kk][pixel]

    int z = blockIdx.z;
    const float* w  = (z == 0) ? wq : (z == 1 ? wk : wv);
    float*       op = (z == 0) ? g_q : (z == 1 ? g_k : g_v);
    int coff        = (z == 0) ? 128 : 0;

    int t    = threadIdx.x;
    int pix0 = blockIdx.x * 64;            // 64 contiguous pixels, within one batch
    int b    = pix0 >> 12;                 // 4096 pixels per image
    int rem0 = pix0 & 4095;

    const float* xbase = fm + ((size_t)(b * 256 + coff) << 12) + rem0;

    int ocb = (t >> 4) << 3;               // 0..120 step 8
    int pxb = (t & 15) << 2;               // 0..60 step 4

    float acc[8][4];
#pragma unroll
    for (int u = 0; u < 8; u++)
#pragma unroll
        for (int p = 0; p < 4; p++) acc[u][p] = 0.f;

    for (int ic0 = 0; ic0 < 128; ic0 += 32) {
        // weights: 128 oc x 32 ic chunk (coalesced along ic)
#pragma unroll
        for (int j = 0; j < 16; j++) {
            int idx = t + j * 256;
            wS[idx >> 5][idx & 31] = w[(idx >> 5) * 128 + ic0 + (idx & 31)];
        }
        // activations: 32 ic x 64 pixels (coalesced along pixel)
#pragma unroll
        for (int j = 0; j < 8; j++) {
            int idx = t + j * 256;
            xS[idx >> 6][idx & 63] =
                xbase[(size_t)(ic0 + (idx >> 6)) * 4096 + (idx & 63)];
        }
        __syncthreads();

#pragma unroll
        for (int kk = 0; kk < 32; kk++) {
            float x0 = xS[kk][pxb + 0];
            float x1 = xS[kk][pxb + 1];
            float x2 = xS[kk][pxb + 2];
            float x3 = xS[kk][pxb + 3];
#pragma unroll
            for (int u = 0; u < 8; u++) {
                float wv_ = wS[ocb + u][kk];
                acc[u][0] += wv_ * x0;
                acc[u][1] += wv_ * x1;
                acc[u][2] += wv_ * x2;
                acc[u][3] += wv_ * x3;
            }
        }
        __syncthreads();
    }

    float* ob = op + ((size_t)b << 19) + rem0;   // b*128*4096
#pragma unroll
    for (int u = 0; u < 8; u++) {
        float4 v = make_float4(acc[u][0], acc[u][1], acc[u][2], acc[u][3]);
        *(float4*)(ob + (size_t)(ocb + u) * 4096 + pxb) = v;
    }
}

// ---------------------------------------------------------------------------
// Kernel 2: fused windowed attention (main 7x7 + refine row/col 15) per group.
// Block = (b, g, 4x32 pixel tile). 128 threads, 1 thread per pixel.
// ---------------------------------------------------------------------------
__global__ __launch_bounds__(128) void attn_kernel(
    const float* __restrict__ relh,
    const float* __restrict__ relw,
    float* __restrict__ out)
{
    extern __shared__ float sh[];
    float* Ks  = sh;                 // 16 * 828
    float* Vs  = sh + 16 * CHS;      // 16 * 828
    float* rhS = sh + 32 * CHS;      // 448
    float* rwS = rhS + 448;          // 448

    int tid = threadIdx.x;
    int bz  = blockIdx.z;
    int b   = bz >> 3;
    int g   = bz & 7;
    int h0  = blockIdx.y * TH;
    int w0  = blockIdx.x * TW;

    size_t chbase = ((size_t)(b * CC + g * CG) << 12);

    // Load K/V halo with zero fill (coalesced along w)
    for (int idx = tid; idx < 16 * CHS; idx += 128) {
        int c   = idx / CHS;
        int rr  = idx - c * CHS;
        int r   = rr / SW;
        int col = rr - r * SW;
        int gh  = h0 - 7 + r;
        int gw  = w0 - 7 + col;
        float kv = 0.f, vv = 0.f;
        if (gh >= 0 && gh < HH && gw >= 0 && gw < WW) {
            size_t off = chbase + ((size_t)c << 12) + gh * WW + gw;
            kv = g_k[off];
            vv = g_v[off];
        }
        Ks[idx] = kv;
        Vs[idx] = vv;
    }
    for (int idx = tid; idx < 448; idx += 128) {
        rhS[idx] = relh[idx];
        rwS[idx] = relw[idx];
    }
    __syncthreads();

    int px = tid & 31;
    int py = tid >> 5;
    int h  = h0 + py;
    int w  = w0 + px;

    float q[16];
#pragma unroll
    for (int c = 0; c < 16; c++)
        q[c] = g_q[chbase + ((size_t)c << 12) + h * WW + w];

    // Separable rel bias: groups 0-3 use rel_h (index i), 4-7 rel_w (index j)
    float bias[7];
#pragma unroll
    for (int i = 0; i < 7; i++) bias[i] = 0.f;
    if (g < 4) {
#pragma unroll 1
        for (int c = 0; c < 16; c++) {
            float qc = q[c];
#pragma unroll
            for (int i = 0; i < 7; i++)
                bias[i] += qc * rhS[(g * 16 + c) * 7 + i];
        }
    } else {
#pragma unroll 1
        for (int c = 0; c < 16; c++) {
            float qc = q[c];
#pragma unroll
            for (int i = 0; i < 7; i++)
                bias[i] += qc * rwS[((g - 4) * 16 + c) * 7 + i];
        }
    }

    // ---- Main 7x7 window ----
    float lg[49];
#pragma unroll
    for (int di = 0; di < 7; di++)
#pragma unroll
        for (int dj = 0; dj < 7; dj++)
            lg[di * 7 + dj] = (g < 4) ? bias[di] : bias[dj];

    int base00 = (py + 4) * SW + (px + 4);
#pragma unroll 1
    for (int c = 0; c < 16; c++) {
        float qc = q[c];
        const float* kb = Ks + c * CHS + base00;
#pragma unroll
        for (int di = 0; di < 7; di++)
#pragma unroll
            for (int dj = 0; dj < 7; dj++)
                lg[di * 7 + dj] += qc * kb[di * SW + dj];
    }

    float m = lg[0];
#pragma unroll
    for (int p = 1; p < 49; p++) m = fmaxf(m, lg[p]);
    float s = 0.f;
#pragma unroll
    for (int p = 0; p < 49; p++) { lg[p] = __expf(lg[p] - m); s += lg[p]; }
    float inv = 1.f / s;

    float o[16];
#pragma unroll
    for (int c = 0; c < 16; c++) o[c] = 0.f;

#pragma unroll
    for (int di = 0; di < 7; di++)
#pragma unroll
        for (int dj = 0; dj < 7; dj++) {
            float a = lg[di * 7 + dj] * inv;
            const float* vb = Vs + base00 + di * SW + dj;
#pragma unroll
            for (int c = 0; c < 16; c++) o[c] += a * vb[c * CHS];
        }

    // ---- Refine: row window (same h, w-7..w+7), no bias ----
    {
        float lr[15];
#pragma unroll
        for (int j = 0; j < 15; j++) lr[j] = 0.f;
        int rbase = (py + 7) * SW + px;
#pragma unroll 1
        for (int c = 0; c < 16; c++) {
            float qc = q[c];
            const float* kb = Ks + c * CHS + rbase;
#pragma unroll
            for (int j = 0; j < 15; j++) lr[j] += qc * kb[j];
        }
        float mr = lr[0];
#pragma unroll
        for (int j = 1; j < 15; j++) mr = fmaxf(mr, lr[j]);
        float sr = 0.f;
#pragma unroll
        for (int j = 0; j < 15; j++) { lr[j] = __expf(lr[j] - mr); sr += lr[j]; }
        float ir = 1.f / sr;
#pragma unroll
        for (int j = 0; j < 15; j++) {
            float a = lr[j] * ir;
            const float* vb = Vs + rbase + j;
#pragma unroll
            for (int c = 0; c < 16; c++) o[c] += a * vb[c * CHS];
        }
    }

    // ---- Refine: column window (same w, h-7..h+7), no bias ----
    {
        float lc[15];
#pragma unroll
        for (int j = 0; j < 15; j++) lc[j] = 0.f;
        int cbase = py * SW + (px + 7);
#pragma unroll 1
        for (int c = 0; c < 16; c++) {
            float qc = q[c];
            const float* kb = Ks + c * CHS + cbase;
#pragma unroll
            for (int j = 0; j < 15; j++) lc[j] += qc * kb[j * SW];
        }
        float mc = lc[0];
#pragma unroll
        for (int j = 1; j < 15; j++) mc = fmaxf(mc, lc[j]);
        float sc = 0.f;
#pragma unroll
        for (int j = 0; j < 15; j++) { lc[j] = __expf(lc[j] - mc); sc += lc[j]; }
        float ic = 1.f / sc;
#pragma unroll
        for (int j = 0; j < 15; j++) {
            float a = lc[j] * ic;
            const float* vb = Vs + cbase + j * SW;
#pragma unroll
            for (int c = 0; c < 16; c++) o[c] += a * vb[c * CHS];
        }
    }

    size_t obase = chbase + h * WW + w;
#pragma unroll
    for (int c = 0; c < 16; c++)
        out[obase + ((size_t)c << 12)] = o[c];
}

// ---------------------------------------------------------------------------
extern "C" void kernel_launch(void* const* d_in, const int* in_sizes, int n_in,
                              void* d_out, int out_size)
{
    const float* fm = (const float*)d_in[0];
    const float* wq = (const float*)d_in[1];
    const float* wk = (const float*)d_in[2];
    const float* wv = (const float*)d_in[3];
    const float* rh = (const float*)d_in[4];
    const float* rw = (const float*)d_in[5];
    float* out = (float*)d_out;

    cudaFuncSetAttribute(attn_kernel,
                         cudaFuncAttributeMaxDynamicSharedMemorySize, SMEM_BYTES);

    dim3 g1(128, 1, 3);                    // 8192 pixels / 64 per block, z = Q/K/V
    qkv_gemm<<<g1, 256>>>(fm, wq, wk, wv);

    dim3 g2(WW / TW, HH / TH, BB * GG);    // (2, 16, 16)
    attn_kernel<<<g2, 128, SMEM_BYTES>>>(rh, rw, out);
}